// round 2
// baseline (speedup 1.0000x reference)
#include <cuda_runtime.h>
#include <math.h>

// Problem constants
#define BATCH 16
#define CH    512
#define DD    4096   // 64*64

// Scratch (allocation-free rule: __device__ globals)
__device__ float g_S [BATCH * CH * CH];   // scaled scores  S[b][c][e]
__device__ float g_Pa[BATCH * CH * CH];   // row softmax    P_a[b][c][e]
__device__ float g_Mb[BATCH * CH * CH];   // col softmax    M[b][c][e] (= P_b transposed-store)

// ---------------- f32x2 packed helpers (sm_100+ PTX) ----------------
__device__ __forceinline__ unsigned long long pack_dup(float x) {
    unsigned long long r;
    asm("mov.b64 %0, {%1, %1};" : "=l"(r) : "f"(x));
    return r;
}
__device__ __forceinline__ unsigned long long pack2f(float lo, float hi) {
    unsigned long long r;
    asm("mov.b64 %0, {%1, %2};" : "=l"(r) : "f"(lo), "f"(hi));
    return r;
}
__device__ __forceinline__ void unpack2f(unsigned long long v, float& lo, float& hi) {
    asm("mov.b64 {%0, %1}, %2;" : "=f"(lo), "=f"(hi) : "l"(v));
}
__device__ __forceinline__ void fma2(unsigned long long& d, unsigned long long a, unsigned long long b) {
    asm("fma.rn.f32x2 %0, %1, %2, %0;" : "+l"(d) : "l"(a), "l"(b));
}

// ---------------- Generic tiled fp32 GEMM ----------------
// C[m][n] = scale * sum_k A(m,k) * B(n,k-ish), 128x128 block tile, 8x8 per thread,
// f32x2 packed accumulators (2 cols per FFMA2).
//
// AMODE 0: A is row-major [M][K] (lda = K-stride)   -> transpose-load into As[k][m]
// AMODE 1: A is stored [K][M] (lda = M-stride)      -> direct load   into As[k][m]
// BMODE 0: B is row-major [N][K]                    -> transpose-load into Bs[k][n]
// BMODE 1: B is stored [K][N]                       -> direct load   into Bs[k][n]
#define BM  128
#define BN  128
#define BKK 32
#define LDT 132   // smem row stride (pad: 132 mod 32 = 4, keeps float4 alignment)

template<int AMODE, int BMODE>
__global__ void __launch_bounds__(256, 2)
gemm_f32(const float* __restrict__ Ag, const float* __restrict__ Bg,
         float* __restrict__ Cg,
         int Kdim, int Ncols, int lda, int ldb, float scale,
         long strideA, long strideB, long strideC)
{
    __shared__ float As[BKK][LDT];
    __shared__ float Bs[BKK][LDT];

    const float* A  = Ag + (long)blockIdx.z * strideA;
    const float* Bp = Bg + (long)blockIdx.z * strideB;
    float*       Cp = Cg + (long)blockIdx.z * strideC;

    const int m0  = blockIdx.y * BM;
    const int n0  = blockIdx.x * BN;
    const int tid = threadIdx.x;
    const int tx  = tid & 15;   // n-tile index
    const int ty  = tid >> 4;   // m-tile index

    unsigned long long acc[8][4];
#pragma unroll
    for (int i = 0; i < 8; i++)
#pragma unroll
        for (int j = 0; j < 4; j++) acc[i][j] = 0ULL;

    for (int k0 = 0; k0 < Kdim; k0 += BKK) {
        // ---- load A tile ----
        if (AMODE == 0) {
#pragma unroll
            for (int it = 0; it < 4; it++) {
                int idx = tid + it * 256;        // 0..1023
                int r   = idx >> 3;              // row (m), 0..127
                int kq  = idx & 7;               // float4 along k
                float4 v = *(const float4*)(A + (long)(m0 + r) * lda + k0 + kq * 4);
                As[kq * 4 + 0][r] = v.x;
                As[kq * 4 + 1][r] = v.y;
                As[kq * 4 + 2][r] = v.z;
                As[kq * 4 + 3][r] = v.w;
            }
        } else {
#pragma unroll
            for (int it = 0; it < 4; it++) {
                int idx = tid + it * 256;
                int p   = idx >> 5;              // k row, 0..31
                int c4  = idx & 31;              // float4 along m
                *(float4*)&As[p][c4 * 4] =
                    *(const float4*)(A + (long)(k0 + p) * lda + m0 + c4 * 4);
            }
        }
        // ---- load B tile ----
        if (BMODE == 0) {
#pragma unroll
            for (int it = 0; it < 4; it++) {
                int idx = tid + it * 256;
                int r   = idx >> 3;
                int kq  = idx & 7;
                float4 v = *(const float4*)(Bp + (long)(n0 + r) * ldb + k0 + kq * 4);
                Bs[kq * 4 + 0][r] = v.x;
                Bs[kq * 4 + 1][r] = v.y;
                Bs[kq * 4 + 2][r] = v.z;
                Bs[kq * 4 + 3][r] = v.w;
            }
        } else {
#pragma unroll
            for (int it = 0; it < 4; it++) {
                int idx = tid + it * 256;
                int p   = idx >> 5;
                int c4  = idx & 31;
                *(float4*)&Bs[p][c4 * 4] =
                    *(const float4*)(Bp + (long)(k0 + p) * ldb + n0 + c4 * 4);
            }
        }
        __syncthreads();

        // ---- compute ----
#pragma unroll
        for (int p = 0; p < BKK; p++) {
            float a[8];
            *(float4*)&a[0] = *(const float4*)&As[p][ty * 8];
            *(float4*)&a[4] = *(const float4*)&As[p][ty * 8 + 4];
            float4 b0 = *(const float4*)&Bs[p][tx * 8];
            float4 b1 = *(const float4*)&Bs[p][tx * 8 + 4];
            unsigned long long bb[4];
            bb[0] = pack2f(b0.x, b0.y);
            bb[1] = pack2f(b0.z, b0.w);
            bb[2] = pack2f(b1.x, b1.y);
            bb[3] = pack2f(b1.z, b1.w);
#pragma unroll
            for (int i = 0; i < 8; i++) {
                unsigned long long av = pack_dup(a[i]);
#pragma unroll
                for (int j = 0; j < 4; j++) fma2(acc[i][j], av, bb[j]);
            }
        }
        __syncthreads();
    }

    // ---- epilogue ----
#pragma unroll
    for (int i = 0; i < 8; i++) {
        int m = m0 + ty * 8 + i;
        float out[8];
#pragma unroll
        for (int j = 0; j < 4; j++) {
            float lo, hi;
            unpack2f(acc[i][j], lo, hi);
            out[j * 2]     = lo * scale;
            out[j * 2 + 1] = hi * scale;
        }
        float* crow = Cp + (long)m * Ncols + n0 + tx * 8;
        *(float4*)&crow[0] = *(float4*)&out[0];
        *(float4*)&crow[4] = *(float4*)&out[4];
    }
}

// ---------------- Row softmax: P_a[b][r][:] = softmax(S[b][r][:]) ----------------
__global__ void row_softmax_k(const float* __restrict__ S, float* __restrict__ P)
{
    const int b = blockIdx.y, r = blockIdx.x;
    const float* row  = S + ((long)b * CH + r) * CH;
    float*       prow = P + ((long)b * CH + r) * CH;
    const int tid = threadIdx.x;   // 256

    float v0 = row[tid], v1 = row[tid + 256];
    float m = fmaxf(v0, v1);
#pragma unroll
    for (int o = 16; o > 0; o >>= 1) m = fmaxf(m, __shfl_xor_sync(0xffffffffu, m, o));

    __shared__ float red[8];
    if ((tid & 31) == 0) red[tid >> 5] = m;
    __syncthreads();
    float mall = red[0];
#pragma unroll
    for (int w = 1; w < 8; w++) mall = fmaxf(mall, red[w]);

    float e0 = expf(v0 - mall), e1 = expf(v1 - mall);
    float s = e0 + e1;
#pragma unroll
    for (int o = 16; o > 0; o >>= 1) s += __shfl_xor_sync(0xffffffffu, s, o);
    __syncthreads();                 // everyone done reading red (max phase)
    if ((tid & 31) == 0) red[tid >> 5] = s;
    __syncthreads();
    float sall = 0.f;
#pragma unroll
    for (int w = 0; w < 8; w++) sall += red[w];

    float inv = 1.0f / sall;
    prow[tid]       = e0 * inv;
    prow[tid + 256] = e1 * inv;
}

// ---------------- Column softmax: M[b][c][e] = softmax over c of S[b][c][e] ------
// 512 threads: 128 columns x 4 row-groups, online (m,s) per group, merged in smem.
__global__ void col_softmax_k(const float* __restrict__ S, float* __restrict__ Mo)
{
    const int b    = blockIdx.y;
    const int tid  = threadIdx.x;      // 512
    const int lane = tid & 127;
    const int g    = tid >> 7;         // row group 0..3
    const int e    = blockIdx.x * 128 + lane;

    const float* Sb = S  + (long)b * CH * CH;
    float*       Mb = Mo + (long)b * CH * CH;

    float m = -INFINITY, s = 0.f;
    for (int c = g * 128; c < g * 128 + 128; c += 4) {
        float v0 = Sb[(long)(c + 0) * CH + e];
        float v1 = Sb[(long)(c + 1) * CH + e];
        float v2 = Sb[(long)(c + 2) * CH + e];
        float v3 = Sb[(long)(c + 3) * CH + e];
        float mn   = fmaxf(fmaxf(v0, v1), fmaxf(v2, v3));
        float mnew = fmaxf(m, mn);
        s = s * expf(m - mnew)
          + expf(v0 - mnew) + expf(v1 - mnew) + expf(v2 - mnew) + expf(v3 - mnew);
        m = mnew;
    }

    __shared__ float sm[4][128];
    __shared__ float ss[4][128];
    sm[g][lane] = m;
    ss[g][lane] = s;
    __syncthreads();

    float M = -INFINITY, Sv = 0.f;
#pragma unroll
    for (int gi = 0; gi < 4; gi++) {
        float mg = sm[gi][lane], sg = ss[gi][lane];
        float Mn = fmaxf(M, mg);
        Sv = Sv * expf(M - Mn) + sg * expf(mg - Mn);
        M = Mn;
    }
    float inv = 1.0f / Sv;

    for (int c = g * 128; c < g * 128 + 128; c++) {
        Mb[(long)c * CH + e] = expf(Sb[(long)c * CH + e] - M) * inv;
    }
}

// ---------------- Launcher ----------------
extern "C" void kernel_launch(void* const* d_in, const int* in_sizes, int n_in,
                              void* d_out, int out_size)
{
    const float* x1 = (const float*)d_in[0];   // q source [16,512,4096]
    const float* x2 = (const float*)d_in[1];   // k source [16,512,4096]
    float* outA = (float*)d_out;
    float* outB = outA + (long)BATCH * CH * DD;

    float *S, *Pa, *Mb;
    cudaGetSymbolAddress((void**)&S,  g_S);
    cudaGetSymbolAddress((void**)&Pa, g_Pa);
    cudaGetSymbolAddress((void**)&Mb, g_Mb);

    const float scale = 1.0f / 64.0f;   // 1/sqrt(4096)
    dim3 blk(256);

    // 1) S = scale * q k^T   (NT GEMM, M=N=512, K=4096)
    gemm_f32<0, 0><<<dim3(CH / BN, CH / BM, BATCH), blk>>>(
        x1, x2, S, DD, CH, DD, DD, scale,
        (long)CH * DD, (long)CH * DD, (long)CH * CH);

    // 2) softmax over rows -> P_a ; softmax over cols -> M
    row_softmax_k<<<dim3(CH, BATCH), 256>>>(S, Pa);
    col_softmax_k<<<dim3(CH / 128, BATCH), 512>>>(S, Mb);

    // 3) out_A = P_a @ k   (NN GEMM, M=512, N=4096, K=512)
    gemm_f32<0, 1><<<dim3(DD / BN, CH / BM, BATCH), blk>>>(
        Pa, x2, outA, CH, DD, CH, DD, 1.0f,
        (long)CH * CH, (long)CH * DD, (long)CH * DD);

    // 4) out_B = M^T @ q    (TN GEMM, M=512, N=4096, K=512)
    gemm_f32<1, 1><<<dim3(DD / BN, CH / BM, BATCH), blk>>>(
        Mb, x1, outB, CH, DD, CH, DD, 1.0f,
        (long)CH * CH, (long)CH * DD, (long)CH * DD);
}

// round 5
// speedup vs baseline: 4.5211x; 4.5211x over previous
#include <cuda_runtime.h>
#include <cuda_fp16.h>
#include <stdint.h>
#include <math.h>

#define BATCH 16
#define CH    512
#define DD    4096

// ------------------- scratch (__device__ globals) -------------------
__device__ __half g_qh[BATCH * CH * DD];   // x1 fp16, [b][c][d]
__device__ __half g_kh[BATCH * CH * DD];   // x2 fp16, [b][e][d]
__device__ __half g_qT[BATCH * DD * CH];   // x1^T fp16, [b][d][c]
__device__ __half g_kT[BATCH * DD * CH];   // x2^T fp16, [b][d][e]
__device__ float  g_S [BATCH * CH * CH];   // scores fp32 [b][c][e]
__device__ __half g_Pa[BATCH * CH * CH];   // row softmax fp16 [b][c][e]
__device__ __half g_MT[BATCH * CH * CH];   // col softmax transposed fp16 [b][e][c]

// ------------------- helpers -------------------
__device__ __forceinline__ unsigned smem_u32(const void* p) {
    unsigned a;
    asm("{ .reg .u64 t; cvta.to.shared.u64 t, %1; cvt.u32.u64 %0, t; }" : "=r"(a) : "l"(p));
    return a;
}

#define CPA16(dst, src)  asm volatile("cp.async.cg.shared.global [%0], [%1], 16;" :: "r"(dst), "l"(src) : "memory")
#define CPA_COMMIT()     asm volatile("cp.async.commit_group;" ::: "memory")
#define CPA_WAITG(n)     asm volatile("cp.async.wait_group %0;" :: "n"(n) : "memory")

#define LDSM_X4(r, a) asm volatile(                                    \
    "ldmatrix.sync.aligned.m8n8.x4.shared.b16 {%0,%1,%2,%3}, [%4];"    \
    : "=r"((r)[0]), "=r"((r)[1]), "=r"((r)[2]), "=r"((r)[3]) : "r"(a))

__device__ __forceinline__ void mma16816(float* c, const unsigned* a,
                                         unsigned b0, unsigned b1) {
    asm volatile(
        "mma.sync.aligned.m16n8k16.row.col.f32.f16.f16.f32 "
        "{%0,%1,%2,%3}, {%4,%5,%6,%7}, {%8,%9}, {%0,%1,%2,%3};"
        : "+f"(c[0]), "+f"(c[1]), "+f"(c[2]), "+f"(c[3])
        : "r"(a[0]), "r"(a[1]), "r"(a[2]), "r"(a[3]), "r"(b0), "r"(b1));
}

// ------------------- convert + transpose: fp32 -> fp16 (and ^T) -------------------
__global__ void convert_transpose(const float* __restrict__ x1, const float* __restrict__ x2,
                                  __half* __restrict__ qh, __half* __restrict__ kh,
                                  __half* __restrict__ qT, __half* __restrict__ kT)
{
    __shared__ float ts[32][33];
    const int z = blockIdx.z, b = z >> 1, w = z & 1;
    const float* X = (w ? x2 : x1) + (long)b * CH * DD;
    __half* H = (w ? kh : qh) + (long)b * CH * DD;
    __half* T = (w ? kT : qT) + (long)b * DD * CH;
    const int d0 = blockIdx.x * 32, c0 = blockIdx.y * 32;
    const int tx = threadIdx.x, ty = threadIdx.y;
#pragma unroll
    for (int j = 0; j < 4; j++) {
        int r = ty + j * 8;
        float v = X[(long)(c0 + r) * DD + d0 + tx];
        ts[r][tx] = v;
        H[(long)(c0 + r) * DD + d0 + tx] = __float2half_rn(v);
    }
    __syncthreads();
#pragma unroll
    for (int j = 0; j < 4; j++) {
        int r = ty + j * 8;
        T[(long)(d0 + r) * CH + c0 + tx] = __float2half_rn(ts[tx][r]);
    }
}

// ------------------- HMMA fp16 GEMM: C[M][N] = scale * A[M][K] @ B[N][K]^T ----------
// A row-major [M][K] (lda), B row-major [N][K] (ldb)  == mma row.col
// 128x128 CTA tile, BK=32, 3-stage cp.async, 256 thr, 8 warps (4m x 2n), warp 32x64.
#define BK        32
#define ROWB      80                      // smem row stride bytes (32h + 8h pad)
#define AT_BYTES  (128 * ROWB)            // 10240
#define STG_BYTES (2 * AT_BYTES)          // 20480 (A then B)
#define NSTAGE    3
#define GEMM_SMEM (NSTAGE * STG_BYTES)    // 61440

__global__ void __launch_bounds__(256)
gemm_mma(const __half* __restrict__ A, const __half* __restrict__ B, float* __restrict__ C,
         int K, int lda, int ldb, int ldc,
         long sA, long sB, long sC, float scale)
{
    extern __shared__ char smem[];
    const unsigned sb = smem_u32(smem);

    const int tid  = threadIdx.x;
    const int wid  = tid >> 5, lane = tid & 31;
    const int wm   = wid & 3, wn = wid >> 2;        // warp grid 4(m) x 2(n)

    const __half* Ab = A + (long)blockIdx.z * sA + (long)(blockIdx.y * 128) * lda;
    const __half* Bb = B + (long)blockIdx.z * sB + (long)(blockIdx.x * 128) * ldb;

    // per-thread load mapping: 512 chunks of 16B per tile, 2 per thread
    const int l_row0 = (tid) >> 2,         l_c0 = (tid) & 3;
    const int l_row1 = (tid + 256) >> 2,   l_c1 = (tid + 256) & 3;

    auto load_stage = [&](int kt, int s) {
        const unsigned base = sb + (unsigned)s * STG_BYTES;
        const __half* Ak = Ab + kt * BK;
        const __half* Bk = Bb + kt * BK;
        CPA16(base + (unsigned)(l_row0 * ROWB + l_c0 * 16),
              (const char*)(Ak + (long)l_row0 * lda) + l_c0 * 16);
        CPA16(base + (unsigned)(l_row1 * ROWB + l_c1 * 16),
              (const char*)(Ak + (long)l_row1 * lda) + l_c1 * 16);
        CPA16(base + AT_BYTES + (unsigned)(l_row0 * ROWB + l_c0 * 16),
              (const char*)(Bk + (long)l_row0 * ldb) + l_c0 * 16);
        CPA16(base + AT_BYTES + (unsigned)(l_row1 * ROWB + l_c1 * 16),
              (const char*)(Bk + (long)l_row1 * ldb) + l_c1 * 16);
    };

    // ldmatrix per-lane intra-stage offsets
    // A frag (m16xk16): row = wm*32 + mi*16 + (lane&7) + ((lane>>3)&1)*8 ; k8 = (lane>>4)*8
    const unsigned a_off = (unsigned)((wm * 32 + (lane & 7) + ((lane >> 3) & 1) * 8) * ROWB
                                      + ((lane >> 4) & 1) * 16);
    // B frag (n16xk16): n = wn*64 + nt*16 + (lane&7) + ((lane>>4)&1)*8 ; k8 = ((lane>>3)&1)*8
    const unsigned b_off = (unsigned)(AT_BYTES
                                      + (wn * 64 + (lane & 7) + ((lane >> 4) & 1) * 8) * ROWB
                                      + ((lane >> 3) & 1) * 16);

    float acc[2][8][4];
#pragma unroll
    for (int i = 0; i < 2; i++)
#pragma unroll
        for (int j = 0; j < 8; j++)
#pragma unroll
            for (int v = 0; v < 4; v++) acc[i][j][v] = 0.f;

    const int NT = K / BK;
    load_stage(0, 0); CPA_COMMIT();
    load_stage(1, 1); CPA_COMMIT();

    for (int kt = 0; kt < NT; kt++) {
        CPA_WAITG(1);
        __syncthreads();
        if (kt + 2 < NT) load_stage(kt + 2, (kt + 2) % NSTAGE);
        CPA_COMMIT();

        const unsigned stg = sb + (unsigned)(kt % NSTAGE) * STG_BYTES;
#pragma unroll
        for (int ks = 0; ks < 2; ks++) {
            unsigned af[2][4], bf[4][4];
#pragma unroll
            for (int mi = 0; mi < 2; mi++)
                LDSM_X4(af[mi], stg + a_off + (unsigned)(mi * 16 * ROWB + ks * 32));
#pragma unroll
            for (int nt = 0; nt < 4; nt++)
                LDSM_X4(bf[nt], stg + b_off + (unsigned)(nt * 16 * ROWB + ks * 32));
#pragma unroll
            for (int mi = 0; mi < 2; mi++)
#pragma unroll
                for (int n8 = 0; n8 < 8; n8++) {
                    const unsigned* bp = bf[n8 >> 1];
                    mma16816(acc[mi][n8], af[mi],
                             bp[(n8 & 1) * 2], bp[(n8 & 1) * 2 + 1]);
                }
        }
    }

    // epilogue: direct fp32 stores
    float* Cb = C + (long)blockIdx.z * sC
                  + (long)(blockIdx.y * 128 + wm * 32) * ldc
                  + blockIdx.x * 128 + wn * 64;
    const int r0 = lane >> 2, c0 = (lane & 3) * 2;
#pragma unroll
    for (int mi = 0; mi < 2; mi++) {
#pragma unroll
        for (int n8 = 0; n8 < 8; n8++) {
            float* p = Cb + (long)(mi * 16 + r0) * ldc + n8 * 8 + c0;
            float2 v0 = { acc[mi][n8][0] * scale, acc[mi][n8][1] * scale };
            float2 v1 = { acc[mi][n8][2] * scale, acc[mi][n8][3] * scale };
            *(float2*)p = v0;
            *(float2*)(p + 8 * (long)ldc) = v1;
        }
    }
}

// ------------------- row softmax (fp16 out) -------------------
__global__ void row_softmax_k(const float* __restrict__ S, __half* __restrict__ P)
{
    const int b = blockIdx.y, r = blockIdx.x;
    const float* row = S + ((long)b * CH + r) * CH;
    __half* prow = P + ((long)b * CH + r) * CH;
    const int tid = threadIdx.x;   // 256

    float v0 = row[tid], v1 = row[tid + 256];
    float m = fmaxf(v0, v1);
#pragma unroll
    for (int o = 16; o > 0; o >>= 1) m = fmaxf(m, __shfl_xor_sync(0xffffffffu, m, o));

    __shared__ float red[8];
    if ((tid & 31) == 0) red[tid >> 5] = m;
    __syncthreads();
    float mall = red[0];
#pragma unroll
    for (int w = 1; w < 8; w++) mall = fmaxf(mall, red[w]);

    float e0 = expf(v0 - mall), e1 = expf(v1 - mall);
    float s = e0 + e1;
#pragma unroll
    for (int o = 16; o > 0; o >>= 1) s += __shfl_xor_sync(0xffffffffu, s, o);
    __syncthreads();
    if ((tid & 31) == 0) red[tid >> 5] = s;
    __syncthreads();
    float sall = 0.f;
#pragma unroll
    for (int w = 0; w < 8; w++) sall += red[w];

    float inv = 1.0f / sall;
    prow[tid]       = __float2half_rn(e0 * inv);
    prow[tid + 256] = __float2half_rn(e1 * inv);
}

// ------------------- col softmax -> transposed fp16: MT[b][e][c] -------------------
__global__ void col_softmax_k(const float* __restrict__ S, __half* __restrict__ MT)
{
    const int b    = blockIdx.y;
    const int tid  = threadIdx.x;      // 512
    const int lane = tid & 127;
    const int g    = tid >> 7;         // row group 0..3
    const int e    = blockIdx.x * 128 + lane;

    const float* Sb = S + (long)b * CH * CH;
    __half* MTb = MT + (long)b * CH * CH;

    float m = -INFINITY, s = 0.f;
    for (int c = g * 128; c < g * 128 + 128; c += 4) {
        float v0 = Sb[(long)(c + 0) * CH + e];
        float v1 = Sb[(long)(c + 1) * CH + e];
        float v2 = Sb[(long)(c + 2) * CH + e];
        float v3 = Sb[(long)(c + 3) * CH + e];
        float mn   = fmaxf(fmaxf(v0, v1), fmaxf(v2, v3));
        float mnew = fmaxf(m, mn);
        s = s * expf(m - mnew)
          + expf(v0 - mnew) + expf(v1 - mnew) + expf(v2 - mnew) + expf(v3 - mnew);
        m = mnew;
    }

    __shared__ float sm[4][128];
    __shared__ float ss[4][128];
    sm[g][lane] = m;
    ss[g][lane] = s;
    __syncthreads();

    float M = -INFINITY, Sv = 0.f;
#pragma unroll
    for (int gi = 0; gi < 4; gi++) {
        float mg = sm[gi][lane], sg = ss[gi][lane];
        float Mn = fmaxf(M, mg);
        Sv = Sv * expf(M - Mn) + sg * expf(mg - Mn);
        M = Mn;
    }
    float inv = 1.0f / Sv;

    __half* orow = MTb + (long)e * CH;
    for (int c = g * 128; c < g * 128 + 128; c += 8) {
        __half2 h[4];
#pragma unroll
        for (int u = 0; u < 4; u++) {
            float va = expf(Sb[(long)(c + 2 * u)     * CH + e] - M) * inv;
            float vb = expf(Sb[(long)(c + 2 * u + 1) * CH + e] - M) * inv;
            h[u] = __floats2half2_rn(va, vb);
        }
        *(uint4*)(orow + c) = *(uint4*)h;
    }
}

// ------------------- launcher -------------------
extern "C" void kernel_launch(void* const* d_in, const int* in_sizes, int n_in,
                              void* d_out, int out_size)
{
    const float* x1 = (const float*)d_in[0];
    const float* x2 = (const float*)d_in[1];
    float* outA = (float*)d_out;
    float* outB = outA + (long)BATCH * CH * DD;

    __half *qh, *kh, *qT, *kT, *Pa, *MT;
    float *S;
    cudaGetSymbolAddress((void**)&qh, g_qh);
    cudaGetSymbolAddress((void**)&kh, g_kh);
    cudaGetSymbolAddress((void**)&qT, g_qT);
    cudaGetSymbolAddress((void**)&kT, g_kT);
    cudaGetSymbolAddress((void**)&S,  g_S);
    cudaGetSymbolAddress((void**)&Pa, g_Pa);
    cudaGetSymbolAddress((void**)&MT, g_MT);

    cudaFuncSetAttribute(gemm_mma, cudaFuncAttributeMaxDynamicSharedMemorySize, GEMM_SMEM);

    // 0) fp32 -> fp16 convert + transposes
    convert_transpose<<<dim3(DD / 32, CH / 32, BATCH * 2), dim3(32, 8)>>>(x1, x2, qh, kh, qT, kT);

    // 1) S = (1/64) * q @ k^T     M=512 N=512 K=4096
    gemm_mma<<<dim3(CH / 128, CH / 128, BATCH), 256, GEMM_SMEM>>>(
        qh, kh, S, DD, DD, DD, CH,
        (long)CH * DD, (long)CH * DD, (long)CH * CH, 1.0f / 64.0f);

    // 2) softmaxes
    row_softmax_k<<<dim3(CH, BATCH), 256>>>(S, Pa);
    col_softmax_k<<<dim3(CH / 128, BATCH), 512>>>(S, MT);

    // 3) outA = Pa @ k            M=512 N=4096 K=512   (B = kT[d][e])
    gemm_mma<<<dim3(DD / 128, CH / 128, BATCH), 256, GEMM_SMEM>>>(
        Pa, kT, outA, CH, CH, CH, DD,
        (long)CH * CH, (long)DD * CH, (long)CH * DD, 1.0f);

    // 4) outB = M^T @ q           M=512 N=4096 K=512   (A = MT[e][c], B = qT[d][c])
    gemm_mma<<<dim3(DD / 128, CH / 128, BATCH), 256, GEMM_SMEM>>>(
        MT, qT, outB, CH, CH, CH, DD,
        (long)CH * CH, (long)DD * CH, (long)CH * DD, 1.0f);
}

// round 6
// speedup vs baseline: 5.4375x; 1.2027x over previous
#include <cuda_runtime.h>
#include <cuda_fp16.h>
#include <stdint.h>
#include <math.h>

#define BATCH 16
#define CH    512
#define DD    4096

// ------------------- scratch (__device__ globals) -------------------
__device__ __half g_qh[BATCH * CH * DD];   // x1 fp16 [b][c][d]
__device__ __half g_kh[BATCH * CH * DD];   // x2 fp16 [b][e][d]
__device__ float  g_S [BATCH * CH * CH];   // scores fp32 [b][c][e]
__device__ __half g_Pa[BATCH * CH * CH];   // row softmax fp16 [b][c][e]
__device__ __half g_Mn[BATCH * CH * CH];   // col softmax fp16, natural layout [b][c][e]

// ------------------- helpers -------------------
__device__ __forceinline__ unsigned smem_u32(const void* p) {
    unsigned a;
    asm("{ .reg .u64 t; cvta.to.shared.u64 t, %1; cvt.u32.u64 %0, t; }" : "=r"(a) : "l"(p));
    return a;
}

#define CPA16(dst, src)  asm volatile("cp.async.cg.shared.global [%0], [%1], 16;" :: "r"(dst), "l"(src) : "memory")
#define CPA_COMMIT()     asm volatile("cp.async.commit_group;" ::: "memory")
#define CPA_WAITG(n)     asm volatile("cp.async.wait_group %0;" :: "n"(n) : "memory")

#define LDSM_X4(r, a) asm volatile(                                    \
    "ldmatrix.sync.aligned.m8n8.x4.shared.b16 {%0,%1,%2,%3}, [%4];"    \
    : "=r"((r)[0]), "=r"((r)[1]), "=r"((r)[2]), "=r"((r)[3]) : "r"(a))
#define LDSM_X4T(r, a) asm volatile(                                   \
    "ldmatrix.sync.aligned.m8n8.x4.trans.shared.b16 {%0,%1,%2,%3}, [%4];" \
    : "=r"((r)[0]), "=r"((r)[1]), "=r"((r)[2]), "=r"((r)[3]) : "r"(a))

__device__ __forceinline__ void mma16816(float* c, const unsigned* a,
                                         unsigned b0, unsigned b1) {
    asm volatile(
        "mma.sync.aligned.m16n8k16.row.col.f32.f16.f16.f32 "
        "{%0,%1,%2,%3}, {%4,%5,%6,%7}, {%8,%9}, {%0,%1,%2,%3};"
        : "+f"(c[0]), "+f"(c[1]), "+f"(c[2]), "+f"(c[3])
        : "r"(a[0]), "r"(a[1]), "r"(a[2]), "r"(a[3]), "r"(b0), "r"(b1));
}

// ------------------- pure fp32 -> fp16 cast (no transpose) -------------------
__global__ void convert_cast(const float* __restrict__ x1, const float* __restrict__ x2,
                             __half* __restrict__ qh, __half* __restrict__ kh)
{
    const long n4 = (long)BATCH * CH * DD / 4;   // float4 count per tensor
    const long stride = (long)gridDim.x * blockDim.x;
    for (long i = (long)blockIdx.x * blockDim.x + threadIdx.x; i < n4; i += stride) {
        float4 v1 = ((const float4*)x1)[i];
        float4 v2 = ((const float4*)x2)[i];
        __half2 h1a = __floats2half2_rn(v1.x, v1.y), h1b = __floats2half2_rn(v1.z, v1.w);
        __half2 h2a = __floats2half2_rn(v2.x, v2.y), h2b = __floats2half2_rn(v2.z, v2.w);
        uint2 o1 = { *(unsigned*)&h1a, *(unsigned*)&h1b };
        uint2 o2 = { *(unsigned*)&h2a, *(unsigned*)&h2b };
        ((uint2*)qh)[i] = o1;
        ((uint2*)kh)[i] = o2;
    }
}

// ------------------- HMMA fp16 GEMM -------------------
// C[M][N] = scale * A @ B with layouts selected per operand:
//   ALAY 0: A row-major [M][K] (lda = K-stride), non-trans ldmatrix
//   ALAY 1: A stored    [K][M] (lda = M-stride), trans ldmatrix
//   BLAY 0: B row-major [N][K] (ldb = K-stride), non-trans ldmatrix
//   BLAY 1: B stored    [K][N] (ldb = N-stride), trans ldmatrix
// 128x128 CTA tile, BK=32, 4-stage cp.async, 256 thr, 8 warps (4m x 2n), warp 32x64.
#define BK      32
#define ROWMK   80     // [rows][K-chunk] tiles: 32h + 8h pad
#define ROWKN   272    // [K][128] tiles: 256B + 16B pad
#define NSTAGE  4

template<int LAY> struct TileBytes { static const int v = 128 * ROWMK; };  // 10240
template<> struct TileBytes<1>     { static const int v = BK * ROWKN;  };  // 8704

template<int ALAY, int BLAY>
__global__ void __launch_bounds__(256, 2)
gemm_mma(const __half* __restrict__ A, const __half* __restrict__ B, float* __restrict__ C,
         int K, int lda, int ldb, int ldc,
         long sA, long sB, long sC, float scale)
{
    constexpr int ATB = TileBytes<ALAY>::v;
    constexpr int BTB = TileBytes<BLAY>::v;
    constexpr int STG = ATB + BTB;

    extern __shared__ char smem[];
    const unsigned sb = smem_u32(smem);

    const int tid  = threadIdx.x;
    const int wid  = tid >> 5, lane = tid & 31;
    const int wm   = wid & 3, wn = wid >> 2;        // warp grid 4(m) x 2(n)

    const int m0 = blockIdx.y * 128, n0 = blockIdx.x * 128;
    const __half* Ab = A + (long)blockIdx.z * sA + (ALAY == 0 ? (long)m0 * lda : (long)m0);
    const __half* Bb = B + (long)blockIdx.z * sB + (BLAY == 0 ? (long)n0 * ldb : (long)n0);

    // loader: 512 16B-chunks per tile, 2 per thread
    auto load_tile = [&](const __half* G, int ld, int kt, unsigned dstBase, int lay) {
#pragma unroll
        for (int h = 0; h < 2; h++) {
            int i = tid + h * 256;
            if (lay == 0) {   // [rows(128)][K]: row-chunk of BK halfs = 4x16B
                int row = i >> 2, c = i & 3;
                CPA16(dstBase + (unsigned)(row * ROWMK + c * 16),
                      (const char*)(G + (long)row * ld + kt * BK) + c * 16);
            } else {          // [K(32)][128]: row of 128 halfs = 16x16B
                int row = i >> 4, c = i & 15;
                CPA16(dstBase + (unsigned)(row * ROWKN + c * 16),
                      (const char*)(G + (long)(kt * BK + row) * ld) + c * 16);
            }
        }
    };
    auto load_stage = [&](int kt, int s) {
        const unsigned base = sb + (unsigned)s * STG;
        load_tile(Ab, lda, kt, base, ALAY);
        load_tile(Bb, ldb, kt, base + ATB, BLAY);
    };

    // ldmatrix per-lane base offsets (within a stage)
    unsigned a_off, b_off;
    if (ALAY == 0)
        a_off = (unsigned)((wm * 32 + (lane & 15)) * ROWMK + ((lane >> 4) & 1) * 16);
    else  // groups: (k0-7,m0) (k0-7,m8) (k8-15,m0) (k8-15,m8)
        a_off = (unsigned)(((lane & 7) + ((lane >> 4) & 1) * 8) * ROWKN
                           + (wm * 32 + ((lane >> 3) & 1) * 8) * 2);
    if (BLAY == 0)
        b_off = (unsigned)(ATB + (wn * 64 + (lane & 7) + ((lane >> 4) & 1) * 8) * ROWMK
                           + ((lane >> 3) & 1) * 16);
    else  // groups: (k0-7,n0) (k8-15,n0) (k0-7,n8) (k8-15,n8)
        b_off = (unsigned)(ATB + ((lane & 7) + ((lane >> 3) & 1) * 8) * ROWKN
                           + (wn * 64 + ((lane >> 4) & 1) * 8) * 2);

    float acc[2][8][4];
#pragma unroll
    for (int i = 0; i < 2; i++)
#pragma unroll
        for (int j = 0; j < 8; j++)
#pragma unroll
            for (int v = 0; v < 4; v++) acc[i][j][v] = 0.f;

    const int NT = K / BK;
    load_stage(0, 0); CPA_COMMIT();
    load_stage(1, 1); CPA_COMMIT();
    load_stage(2, 2); CPA_COMMIT();

    for (int kt = 0; kt < NT; kt++) {
        CPA_WAITG(2);
        __syncthreads();
        if (kt + 3 < NT) load_stage(kt + 3, (kt + 3) & (NSTAGE - 1));
        CPA_COMMIT();

        const unsigned stg = sb + (unsigned)(kt & (NSTAGE - 1)) * STG;
#pragma unroll
        for (int ks = 0; ks < 2; ks++) {
            unsigned af[2][4], bf[4][4];
#pragma unroll
            for (int mi = 0; mi < 2; mi++) {
                if (ALAY == 0)
                    LDSM_X4(af[mi], stg + a_off + (unsigned)(mi * 16 * ROWMK + ks * 32));
                else
                    LDSM_X4T(af[mi], stg + a_off + (unsigned)(ks * 16 * ROWKN + mi * 32));
            }
#pragma unroll
            for (int nt = 0; nt < 4; nt++) {
                if (BLAY == 0)
                    LDSM_X4(bf[nt], stg + b_off + (unsigned)(nt * 16 * ROWMK + ks * 32));
                else
                    LDSM_X4T(bf[nt], stg + b_off + (unsigned)(ks * 16 * ROWKN + nt * 32));
            }
#pragma unroll
            for (int mi = 0; mi < 2; mi++)
#pragma unroll
                for (int n8 = 0; n8 < 8; n8++) {
                    const unsigned* bp = bf[n8 >> 1];
                    mma16816(acc[mi][n8], af[mi],
                             bp[(n8 & 1) * 2], bp[(n8 & 1) * 2 + 1]);
                }
        }
    }

    // epilogue: direct fp32 stores
    float* Cb = C + (long)blockIdx.z * sC
                  + (long)(m0 + wm * 32) * ldc + n0 + wn * 64;
    const int r0 = lane >> 2, c0 = (lane & 3) * 2;
#pragma unroll
    for (int mi = 0; mi < 2; mi++) {
#pragma unroll
        for (int n8 = 0; n8 < 8; n8++) {
            float* p = Cb + (long)(mi * 16 + r0) * ldc + n8 * 8 + c0;
            float2 v0 = { acc[mi][n8][0] * scale, acc[mi][n8][1] * scale };
            float2 v1 = { acc[mi][n8][2] * scale, acc[mi][n8][3] * scale };
            *(float2*)p = v0;
            *(float2*)(p + 8 * (long)ldc) = v1;
        }
    }
}

// ------------------- row softmax (fp16 out) -------------------
__global__ void row_softmax_k(const float* __restrict__ S, __half* __restrict__ P)
{
    const int b = blockIdx.y, r = blockIdx.x;
    const float* row = S + ((long)b * CH + r) * CH;
    __half* prow = P + ((long)b * CH + r) * CH;
    const int tid = threadIdx.x;   // 256

    float v0 = row[tid], v1 = row[tid + 256];
    float m = fmaxf(v0, v1);
#pragma unroll
    for (int o = 16; o > 0; o >>= 1) m = fmaxf(m, __shfl_xor_sync(0xffffffffu, m, o));

    __shared__ float red[8];
    if ((tid & 31) == 0) red[tid >> 5] = m;
    __syncthreads();
    float mall = red[0];
#pragma unroll
    for (int w = 1; w < 8; w++) mall = fmaxf(mall, red[w]);

    float e0 = expf(v0 - mall), e1 = expf(v1 - mall);
    float s = e0 + e1;
#pragma unroll
    for (int o = 16; o > 0; o >>= 1) s += __shfl_xor_sync(0xffffffffu, s, o);
    __syncthreads();
    if ((tid & 31) == 0) red[tid >> 5] = s;
    __syncthreads();
    float sall = 0.f;
#pragma unroll
    for (int w = 0; w < 8; w++) sall += red[w];

    float inv = 1.0f / sall;
    prow[tid]       = __float2half_rn(e0 * inv);
    prow[tid + 256] = __float2half_rn(e1 * inv);
}

// ------------------- col softmax, natural-layout output Mn[b][c][e] -------------------
// block: 512 thr = 64 e-lanes x 8 c-groups of 64; grid (CH/64, BATCH) = 128 blocks
__global__ void col_softmax_k(const float* __restrict__ S, __half* __restrict__ Mn)
{
    const int b    = blockIdx.y;
    const int tid  = threadIdx.x;      // 512
    const int lane = tid & 63;
    const int g    = tid >> 6;         // c-group 0..7
    const int e    = blockIdx.x * 64 + lane;

    const float* Sb = S + (long)b * CH * CH;
    __half* Mb = Mn + (long)b * CH * CH;

    float m = -INFINITY, s = 0.f;
    for (int c = g * 64; c < g * 64 + 64; c += 4) {
        float v0 = Sb[(long)(c + 0) * CH + e];
        float v1 = Sb[(long)(c + 1) * CH + e];
        float v2 = Sb[(long)(c + 2) * CH + e];
        float v3 = Sb[(long)(c + 3) * CH + e];
        float mn   = fmaxf(fmaxf(v0, v1), fmaxf(v2, v3));
        float mnew = fmaxf(m, mn);
        s = s * expf(m - mnew)
          + expf(v0 - mnew) + expf(v1 - mnew) + expf(v2 - mnew) + expf(v3 - mnew);
        m = mnew;
    }

    __shared__ float sm[8][64];
    __shared__ float ss[8][64];
    sm[g][lane] = m;
    ss[g][lane] = s;
    __syncthreads();

    float M = -INFINITY, Sv = 0.f;
#pragma unroll
    for (int gi = 0; gi < 8; gi++) {
        float mg = sm[gi][lane], sg = ss[gi][lane];
        float Mn2 = fmaxf(M, mg);
        Sv = Sv * expf(M - Mn2) + sg * expf(mg - Mn2);
        M = Mn2;
    }
    float inv = 1.0f / Sv;

    for (int c = g * 64; c < g * 64 + 64; c++) {
        Mb[(long)c * CH + e] = __float2half_rn(expf(Sb[(long)c * CH + e] - M) * inv);
    }
}

// ------------------- launcher -------------------
extern "C" void kernel_launch(void* const* d_in, const int* in_sizes, int n_in,
                              void* d_out, int out_size)
{
    const float* x1 = (const float*)d_in[0];
    const float* x2 = (const float*)d_in[1];
    float* outA = (float*)d_out;
    float* outB = outA + (long)BATCH * CH * DD;

    __half *qh, *kh, *Pa, *Mn;
    float *S;
    cudaGetSymbolAddress((void**)&qh, g_qh);
    cudaGetSymbolAddress((void**)&kh, g_kh);
    cudaGetSymbolAddress((void**)&S,  g_S);
    cudaGetSymbolAddress((void**)&Pa, g_Pa);
    cudaGetSymbolAddress((void**)&Mn, g_Mn);

    constexpr int SM00 = NSTAGE * (TileBytes<0>::v + TileBytes<0>::v);  // 81920
    constexpr int SM01 = NSTAGE * (TileBytes<0>::v + TileBytes<1>::v);  // 75776
    constexpr int SM11 = NSTAGE * (TileBytes<1>::v + TileBytes<1>::v);  // 69632
    cudaFuncSetAttribute(gemm_mma<0, 0>, cudaFuncAttributeMaxDynamicSharedMemorySize, SM00);
    cudaFuncSetAttribute(gemm_mma<0, 1>, cudaFuncAttributeMaxDynamicSharedMemorySize, SM01);
    cudaFuncSetAttribute(gemm_mma<1, 1>, cudaFuncAttributeMaxDynamicSharedMemorySize, SM11);

    // 0) fp32 -> fp16 cast
    convert_cast<<<8192, 256>>>(x1, x2, qh, kh);

    // 1) S = (1/64) * q @ k^T     M=512 N=512 K=4096; A[M][K], B[N][K]
    gemm_mma<0, 0><<<dim3(CH / 128, CH / 128, BATCH), 256, SM00>>>(
        qh, kh, S, DD, DD, DD, CH,
        (long)CH * DD, (long)CH * DD, (long)CH * CH, 1.0f / 64.0f);

    // 2) softmaxes
    row_softmax_k<<<dim3(CH, BATCH), 256>>>(S, Pa);
    col_softmax_k<<<dim3(CH / 64, BATCH), 512>>>(S, Mn);

    // 3) outA = Pa @ k            M=512 N=4096 K=512; A=Pa[M][K], B=kh[K][N]
    gemm_mma<0, 1><<<dim3(DD / 128, CH / 128, BATCH), 256, SM01>>>(
        Pa, kh, outA, CH, CH, DD, DD,
        (long)CH * CH, (long)CH * DD, (long)CH * DD, 1.0f);

    // 4) outB = M^T @ q           M=512(e) N=4096(d) K=512(c); A=Mn[K][M], B=qh[K][N]
    gemm_mma<1, 1><<<dim3(DD / 128, CH / 128, BATCH), 256, SM11>>>(
        Mn, qh, outB, CH, CH, DD, DD,
        (long)CH * CH, (long)CH * DD, (long)CH * DD, 1.0f);
}

// round 7
// speedup vs baseline: 5.8537x; 1.0765x over previous
#include <cuda_runtime.h>
#include <cuda_fp16.h>
#include <stdint.h>
#include <math.h>

#define BATCH 16
#define CH    512
#define DD    4096

// ------------------- scratch (__device__ globals) -------------------
__device__ __half g_qh[BATCH * CH * DD];   // x1 fp16 [b][c][d]
__device__ __half g_kh[BATCH * CH * DD];   // x2 fp16 [b][e][d]
__device__ float  g_S [BATCH * CH * CH];   // scores fp32 [b][c][e]
__device__ __half g_Pa[BATCH * CH * CH];   // row softmax fp16 [b][c][e]
__device__ __half g_Mn[BATCH * CH * CH];   // col softmax fp16, natural layout [b][c][e]

// ------------------- helpers -------------------
__device__ __forceinline__ unsigned smem_u32(const void* p) {
    unsigned a;
    asm("{ .reg .u64 t; cvta.to.shared.u64 t, %1; cvt.u32.u64 %0, t; }" : "=r"(a) : "l"(p));
    return a;
}

#define CPA16(dst, src)  asm volatile("cp.async.cg.shared.global [%0], [%1], 16;" :: "r"(dst), "l"(src) : "memory")
#define CPA_COMMIT()     asm volatile("cp.async.commit_group;" ::: "memory")
#define CPA_WAITG(n)     asm volatile("cp.async.wait_group %0;" :: "n"(n) : "memory")

#define LDSM_X4(r, a) asm volatile(                                    \
    "ldmatrix.sync.aligned.m8n8.x4.shared.b16 {%0,%1,%2,%3}, [%4];"    \
    : "=r"((r)[0]), "=r"((r)[1]), "=r"((r)[2]), "=r"((r)[3]) : "r"(a))
#define LDSM_X4T(r, a) asm volatile(                                   \
    "ldmatrix.sync.aligned.m8n8.x4.trans.shared.b16 {%0,%1,%2,%3}, [%4];" \
    : "=r"((r)[0]), "=r"((r)[1]), "=r"((r)[2]), "=r"((r)[3]) : "r"(a))

__device__ __forceinline__ void mma16816(float* c, const unsigned* a,
                                         unsigned b0, unsigned b1) {
    asm volatile(
        "mma.sync.aligned.m16n8k16.row.col.f32.f16.f16.f32 "
        "{%0,%1,%2,%3}, {%4,%5,%6,%7}, {%8,%9}, {%0,%1,%2,%3};"
        : "+f"(c[0]), "+f"(c[1]), "+f"(c[2]), "+f"(c[3])
        : "r"(a[0]), "r"(a[1]), "r"(a[2]), "r"(a[3]), "r"(b0), "r"(b1));
}

// ------------------- pure fp32 -> fp16 cast -------------------
__global__ void convert_cast(const float* __restrict__ x1, const float* __restrict__ x2,
                             __half* __restrict__ qh, __half* __restrict__ kh)
{
    const long n4 = (long)BATCH * CH * DD / 4;
    const long stride = (long)gridDim.x * blockDim.x;
    for (long i = (long)blockIdx.x * blockDim.x + threadIdx.x; i < n4; i += stride) {
        float4 v1 = ((const float4*)x1)[i];
        float4 v2 = ((const float4*)x2)[i];
        __half2 h1a = __floats2half2_rn(v1.x, v1.y), h1b = __floats2half2_rn(v1.z, v1.w);
        __half2 h2a = __floats2half2_rn(v2.x, v2.y), h2b = __floats2half2_rn(v2.z, v2.w);
        uint2 o1 = { *(unsigned*)&h1a, *(unsigned*)&h1b };
        uint2 o2 = { *(unsigned*)&h2a, *(unsigned*)&h2b };
        ((uint2*)qh)[i] = o1;
        ((uint2*)kh)[i] = o2;
    }
}

// ------------------- HMMA fp16 GEMM -------------------
// C[M][N] = scale * A @ B; operand layouts:
//   ALAY 0: A row-major [M][K], non-trans ldmatrix    ALAY 1: A stored [K][M], trans
//   BLAY 0: B row-major [N][K], non-trans ldmatrix    BLAY 1: B stored [K][N], trans
// 128x128 CTA tile, BK=32, 4-stage cp.async, 128 thr, 4 warps (2m x 2n), warp 64x64.
#define BK      32
#define ROWMK   80     // [rows][K-chunk] tiles: 32h + 8h pad
#define ROWKN   272    // [K][128] tiles: 256B + 16B pad
#define NSTAGE  4

template<int LAY> struct TileBytes { static const int v = 128 * ROWMK; };  // 10240
template<> struct TileBytes<1>     { static const int v = BK * ROWKN;  };  // 8704

template<int ALAY, int BLAY>
__global__ void __launch_bounds__(128, 2)
gemm_mma(const __half* __restrict__ A, const __half* __restrict__ B, float* __restrict__ C,
         int K, int lda, int ldb, int ldc,
         long sA, long sB, long sC, float scale)
{
    constexpr int ATB = TileBytes<ALAY>::v;
    constexpr int BTB = TileBytes<BLAY>::v;
    constexpr int STG = ATB + BTB;

    extern __shared__ char smem[];
    const unsigned sb = smem_u32(smem);

    const int tid  = threadIdx.x;
    const int wid  = tid >> 5, lane = tid & 31;
    const int wm   = wid & 1, wn = wid >> 1;        // warp grid 2(m) x 2(n), 64x64 tiles

    const int m0 = blockIdx.y * 128, n0 = blockIdx.x * 128;
    const __half* Ab = A + (long)blockIdx.z * sA + (ALAY == 0 ? (long)m0 * lda : (long)m0);
    const __half* Bb = B + (long)blockIdx.z * sB + (BLAY == 0 ? (long)n0 * ldb : (long)n0);

    // loader: 512 16B-chunks per tile, 4 per thread (128 threads)
    auto load_tile = [&](const __half* G, int ld, int kt, unsigned dstBase, int lay) {
#pragma unroll
        for (int h = 0; h < 4; h++) {
            int i = tid + h * 128;
            if (lay == 0) {   // [rows(128)][K]: row-chunk of BK halfs = 4x16B
                int row = i >> 2, c = i & 3;
                CPA16(dstBase + (unsigned)(row * ROWMK + c * 16),
                      (const char*)(G + (long)row * ld + kt * BK) + c * 16);
            } else {          // [K(32)][128]: row of 128 halfs = 16x16B
                int row = i >> 4, c = i & 15;
                CPA16(dstBase + (unsigned)(row * ROWKN + c * 16),
                      (const char*)(G + (long)(kt * BK + row) * ld) + c * 16);
            }
        }
    };
    auto load_stage = [&](int kt, int s) {
        const unsigned base = sb + (unsigned)s * STG;
        load_tile(Ab, lda, kt, base, ALAY);
        load_tile(Bb, ldb, kt, base + ATB, BLAY);
    };

    // ldmatrix per-lane base offsets (within a stage)
    unsigned a_off, b_off;
    if (ALAY == 0)
        a_off = (unsigned)((wm * 64 + (lane & 15)) * ROWMK + ((lane >> 4) & 1) * 16);
    else  // trans groups: (k0-7,m0) (k0-7,m8) (k8-15,m0) (k8-15,m8)
        a_off = (unsigned)(((lane & 7) + ((lane >> 4) & 1) * 8) * ROWKN
                           + (wm * 64 + ((lane >> 3) & 1) * 8) * 2);
    if (BLAY == 0)
        b_off = (unsigned)(ATB + (wn * 64 + (lane & 7) + ((lane >> 4) & 1) * 8) * ROWMK
                           + ((lane >> 3) & 1) * 16);
    else  // trans groups: (k0-7,n0) (k8-15,n0) (k0-7,n8) (k8-15,n8)
        b_off = (unsigned)(ATB + ((lane & 7) + ((lane >> 3) & 1) * 8) * ROWKN
                           + (wn * 64 + ((lane >> 4) & 1) * 8) * 2);

    float acc[4][8][4];
#pragma unroll
    for (int i = 0; i < 4; i++)
#pragma unroll
        for (int j = 0; j < 8; j++)
#pragma unroll
            for (int v = 0; v < 4; v++) acc[i][j][v] = 0.f;

    const int NT = K / BK;
    load_stage(0, 0); CPA_COMMIT();
    load_stage(1, 1); CPA_COMMIT();
    load_stage(2, 2); CPA_COMMIT();

    for (int kt = 0; kt < NT; kt++) {
        CPA_WAITG(2);
        __syncthreads();
        if (kt + 3 < NT) load_stage(kt + 3, (kt + 3) & (NSTAGE - 1));
        CPA_COMMIT();

        const unsigned stg = sb + (unsigned)(kt & (NSTAGE - 1)) * STG;
#pragma unroll
        for (int ks = 0; ks < 2; ks++) {
            unsigned af[4][4], bf[4][4];
#pragma unroll
            for (int mi = 0; mi < 4; mi++) {
                if (ALAY == 0)
                    LDSM_X4(af[mi], stg + a_off + (unsigned)(mi * 16 * ROWMK + ks * 32));
                else
                    LDSM_X4T(af[mi], stg + a_off + (unsigned)(ks * 16 * ROWKN + mi * 32));
            }
#pragma unroll
            for (int nt = 0; nt < 4; nt++) {
                if (BLAY == 0)
                    LDSM_X4(bf[nt], stg + b_off + (unsigned)(nt * 16 * ROWMK + ks * 32));
                else
                    LDSM_X4T(bf[nt], stg + b_off + (unsigned)(ks * 16 * ROWKN + nt * 32));
            }
#pragma unroll
            for (int mi = 0; mi < 4; mi++)
#pragma unroll
                for (int n8 = 0; n8 < 8; n8++) {
                    const unsigned* bp = bf[n8 >> 1];
                    mma16816(acc[mi][n8], af[mi],
                             bp[(n8 & 1) * 2], bp[(n8 & 1) * 2 + 1]);
                }
        }
    }

    // epilogue: direct fp32 stores
    float* Cb = C + (long)blockIdx.z * sC
                  + (long)(m0 + wm * 64) * ldc + n0 + wn * 64;
    const int r0 = lane >> 2, c0 = (lane & 3) * 2;
#pragma unroll
    for (int mi = 0; mi < 4; mi++) {
#pragma unroll
        for (int n8 = 0; n8 < 8; n8++) {
            float* p = Cb + (long)(mi * 16 + r0) * ldc + n8 * 8 + c0;
            float2 v0 = { acc[mi][n8][0] * scale, acc[mi][n8][1] * scale };
            float2 v1 = { acc[mi][n8][2] * scale, acc[mi][n8][3] * scale };
            *(float2*)p = v0;
            *(float2*)(p + 8 * (long)ldc) = v1;
        }
    }
}

// ------------------- row softmax (fp16 out) -------------------
__global__ void row_softmax_k(const float* __restrict__ S, __half* __restrict__ P)
{
    const int b = blockIdx.y, r = blockIdx.x;
    const float* row = S + ((long)b * CH + r) * CH;
    __half* prow = P + ((long)b * CH + r) * CH;
    const int tid = threadIdx.x;   // 256

    float v0 = row[tid], v1 = row[tid + 256];
    float m = fmaxf(v0, v1);
#pragma unroll
    for (int o = 16; o > 0; o >>= 1) m = fmaxf(m, __shfl_xor_sync(0xffffffffu, m, o));

    __shared__ float red[8];
    if ((tid & 31) == 0) red[tid >> 5] = m;
    __syncthreads();
    float mall = red[0];
#pragma unroll
    for (int w = 1; w < 8; w++) mall = fmaxf(mall, red[w]);

    float e0 = expf(v0 - mall), e1 = expf(v1 - mall);
    float s = e0 + e1;
#pragma unroll
    for (int o = 16; o > 0; o >>= 1) s += __shfl_xor_sync(0xffffffffu, s, o);
    __syncthreads();
    if ((tid & 31) == 0) red[tid >> 5] = s;
    __syncthreads();
    float sall = 0.f;
#pragma unroll
    for (int w = 0; w < 8; w++) sall += red[w];

    float inv = 1.0f / sall;
    prow[tid]       = __float2half_rn(e0 * inv);
    prow[tid + 256] = __float2half_rn(e1 * inv);
}

// ------------------- col softmax, natural-layout output Mn[b][c][e] -------------------
__global__ void col_softmax_k(const float* __restrict__ S, __half* __restrict__ Mn)
{
    const int b    = blockIdx.y;
    const int tid  = threadIdx.x;      // 512
    const int lane = tid & 63;
    const int g    = tid >> 6;         // c-group 0..7
    const int e    = blockIdx.x * 64 + lane;

    const float* Sb = S + (long)b * CH * CH;
    __half* Mb = Mn + (long)b * CH * CH;

    float m = -INFINITY, s = 0.f;
    for (int c = g * 64; c < g * 64 + 64; c += 4) {
        float v0 = Sb[(long)(c + 0) * CH + e];
        float v1 = Sb[(long)(c + 1) * CH + e];
        float v2 = Sb[(long)(c + 2) * CH + e];
        float v3 = Sb[(long)(c + 3) * CH + e];
        float mn   = fmaxf(fmaxf(v0, v1), fmaxf(v2, v3));
        float mnew = fmaxf(m, mn);
        s = s * expf(m - mnew)
          + expf(v0 - mnew) + expf(v1 - mnew) + expf(v2 - mnew) + expf(v3 - mnew);
        m = mnew;
    }

    __shared__ float sm[8][64];
    __shared__ float ss[8][64];
    sm[g][lane] = m;
    ss[g][lane] = s;
    __syncthreads();

    float M = -INFINITY, Sv = 0.f;
#pragma unroll
    for (int gi = 0; gi < 8; gi++) {
        float mg = sm[gi][lane], sg = ss[gi][lane];
        float Mn2 = fmaxf(M, mg);
        Sv = Sv * expf(M - Mn2) + sg * expf(mg - Mn2);
        M = Mn2;
    }
    float inv = 1.0f / Sv;

    for (int c = g * 64; c < g * 64 + 64; c++) {
        Mb[(long)c * CH + e] = __float2half_rn(expf(Sb[(long)c * CH + e] - M) * inv);
    }
}

// ------------------- launcher -------------------
extern "C" void kernel_launch(void* const* d_in, const int* in_sizes, int n_in,
                              void* d_out, int out_size)
{
    const float* x1 = (const float*)d_in[0];
    const float* x2 = (const float*)d_in[1];
    float* outA = (float*)d_out;
    float* outB = outA + (long)BATCH * CH * DD;

    __half *qh, *kh, *Pa, *Mn;
    float *S;
    cudaGetSymbolAddress((void**)&qh, g_qh);
    cudaGetSymbolAddress((void**)&kh, g_kh);
    cudaGetSymbolAddress((void**)&S,  g_S);
    cudaGetSymbolAddress((void**)&Pa, g_Pa);
    cudaGetSymbolAddress((void**)&Mn, g_Mn);

    constexpr int SM00 = NSTAGE * (TileBytes<0>::v + TileBytes<0>::v);  // 81920
    constexpr int SM01 = NSTAGE * (TileBytes<0>::v + TileBytes<1>::v);  // 75776
    constexpr int SM11 = NSTAGE * (TileBytes<1>::v + TileBytes<1>::v);  // 69632
    cudaFuncSetAttribute(gemm_mma<0, 0>, cudaFuncAttributeMaxDynamicSharedMemorySize, SM00);
    cudaFuncSetAttribute(gemm_mma<0, 1>, cudaFuncAttributeMaxDynamicSharedMemorySize, SM01);
    cudaFuncSetAttribute(gemm_mma<1, 1>, cudaFuncAttributeMaxDynamicSharedMemorySize, SM11);

    // 0) fp32 -> fp16 cast
    convert_cast<<<8192, 256>>>(x1, x2, qh, kh);

    // 1) S = (1/64) * q @ k^T     M=512 N=512 K=4096; A[M][K], B[N][K]
    gemm_mma<0, 0><<<dim3(CH / 128, CH / 128, BATCH), 128, SM00>>>(
        qh, kh, S, DD, DD, DD, CH,
        (long)CH * DD, (long)CH * DD, (long)CH * CH, 1.0f / 64.0f);

    // 2) softmaxes
    row_softmax_k<<<dim3(CH, BATCH), 256>>>(S, Pa);
    col_softmax_k<<<dim3(CH / 64, BATCH), 512>>>(S, Mn);

    // 3) outA = Pa @ k            M=512 N=4096 K=512; A=Pa[M][K], B=kh[K][N]
    gemm_mma<0, 1><<<dim3(DD / 128, CH / 128, BATCH), 128, SM01>>>(
        Pa, kh, outA, CH, CH, DD, DD,
        (long)CH * CH, (long)CH * DD, (long)CH * DD, 1.0f);

    // 4) outB = M^T @ q           M=512(e) N=4096(d) K=512(c); A=Mn[K][M], B=qh[K][N]
    gemm_mma<1, 1><<<dim3(DD / 128, CH / 128, BATCH), 128, SM11>>>(
        Mn, qh, outB, CH, CH, DD, DD,
        (long)CH * CH, (long)CH * DD, (long)CH * DD, 1.0f);
}